// round 1
// baseline (speedup 1.0000x reference)
#include <cuda_runtime.h>
#include <cuda_bf16.h>

#define C_CLASSES 6625
#define D_DIM     96
#define NTHREADS  256
#define EPSV      1e-7f
#define INFV      1e11f

// Output picks up (C-1)*EPS from clip() acting on the masked-out zeros:
// loss = sum_n clip(dist_n)/N + (C-1)*EPS
__global__ void cl_init_out(float* out) {
    out[0] = (float)(C_CLASSES - 1) * EPSV;
}

__global__ __launch_bounds__(NTHREADS, 4)
void center_loss_kernel(const float* __restrict__ features,  // [N, 96]
                        const float* __restrict__ predicts,  // [N, 6625]
                        const float* __restrict__ centers,   // [6625, 96]
                        float* __restrict__ out,
                        int N)
{
    const int n   = blockIdx.x;
    const int tid = threadIdx.x;
    const float* row = predicts + (size_t)n * C_CLASSES;

    // ---- per-thread strided argmax (coalesced; independent loads -> high MLP)
    float best = -3.402823466e38f;
    int   bidx = C_CLASSES;  // larger than any valid idx, for tie-break
    #pragma unroll 4
    for (int c = tid; c < C_CLASSES; c += NTHREADS) {
        float v = __ldg(row + c);
        if (v > best) { best = v; bidx = c; }
    }

    // ---- block tree-reduce (val, idx); first-occurrence tie-break (min idx)
    __shared__ float svals[NTHREADS];
    __shared__ int   sidx[NTHREADS];
    svals[tid] = best;
    sidx[tid]  = bidx;
    __syncthreads();
    #pragma unroll
    for (int s = NTHREADS / 2; s > 0; s >>= 1) {
        if (tid < s) {
            float v2 = svals[tid + s];
            int   i2 = sidx[tid + s];
            if (v2 > svals[tid] || (v2 == svals[tid] && i2 < sidx[tid])) {
                svals[tid] = v2;
                sidx[tid]  = i2;
            }
        }
        __syncthreads();
    }
    const int label = sidx[0];

    // ---- squared distance to the label center over D=96
    __shared__ float sterm[D_DIM];
    if (tid < D_DIM) {
        float f = __ldg(features + (size_t)n * D_DIM + tid);
        float c = __ldg(centers + (size_t)label * D_DIM + tid);
        float d = f - c;
        sterm[tid] = d * d;
    }
    __syncthreads();

    if (tid == 0) {
        float dist = 0.0f;
        #pragma unroll
        for (int i = 0; i < D_DIM; i++) dist += sterm[i];
        dist = fminf(fmaxf(dist, EPSV), INFV);
        atomicAdd(out, dist / (float)N);
    }
}

extern "C" void kernel_launch(void* const* d_in, const int* in_sizes, int n_in,
                              void* d_out, int out_size) {
    const float* features = (const float*)d_in[0];  // [B,T,D] fp32
    const float* predicts = (const float*)d_in[1];  // [B,T,C] fp32
    const float* centers  = (const float*)d_in[2];  // [C,D]   fp32
    float* out = (float*)d_out;

    const int N = in_sizes[0] / D_DIM;  // B*T = 8192

    cl_init_out<<<1, 1>>>(out);
    center_loss_kernel<<<N, NTHREADS>>>(features, predicts, centers, out, N);
}

// round 2
// speedup vs baseline: 1.2528x; 1.2528x over previous
#include <cuda_runtime.h>
#include <cuda_bf16.h>
#include <cstdint>

#define C_CLASSES 6625
#define D_DIM     96
#define NTHREADS  256
#define NWARPS    (NTHREADS / 32)
#define MAXV      7          // ceil(1656 / 256)
#define EPSV      1e-7f
#define INFV      1e11f

// clip() applied to the masked-out zeros contributes (C-1)*EPS exactly.
__global__ void cl_init_out(float* out) {
    out[0] = (float)(C_CLASSES - 1) * EPSV;
}

__global__ __launch_bounds__(NTHREADS, 4)
void center_loss_kernel(const float* __restrict__ features,  // [N, 96]
                        const float* __restrict__ predicts,  // [N, 6625]
                        const float* __restrict__ centers,   // [6625, 96]
                        float* __restrict__ out,
                        int N)
{
    const int n   = blockIdx.x;
    const int tid = threadIdx.x;
    const float* row = predicts + (size_t)n * C_CLASSES;

    // Row stride 6625 floats = 26500 B is only 4B-aligned -> per-row
    // alignment prologue so the vector body can use LDG.128 safely.
    const int mis = ((int)((uintptr_t)row >> 2)) & 3;   // misaligned floats
    const int p   = (4 - mis) & 3;                      // scalar prologue count
    const int nv  = (C_CLASSES - p) >> 2;               // float4 count
    const int tail_start = p + (nv << 2);

    const float4* vrow = (const float4*)(row + p);

    float best = -3.402823466e38f;
    int   bidx = C_CLASSES;

    // Phase 1: batch-load up to 7 independent float4s (high MLP).
    float4 buf[MAXV];
    #pragma unroll
    for (int i = 0; i < MAXV; i++) {
        int v = tid + i * NTHREADS;
        if (v < nv) buf[i] = __ldg(vrow + v);
    }
    // Phase 2: compare chain (ascending index order within thread -> strict >
    // preserves first-occurrence tie-break inside a thread).
    #pragma unroll
    for (int i = 0; i < MAXV; i++) {
        int v = tid + i * NTHREADS;
        if (v < nv) {
            const int base = p + (v << 2);
            float4 q = buf[i];
            if (q.x > best) { best = q.x; bidx = base;     }
            if (q.y > best) { best = q.y; bidx = base + 1; }
            if (q.z > best) { best = q.z; bidx = base + 2; }
            if (q.w > best) { best = q.w; bidx = base + 3; }
        }
    }
    // Scalar prologue (indices smaller than all vector indices: need tie-break).
    if (tid < p) {
        float v = __ldg(row + tid);
        if (v > best || (v == best && tid < bidx)) { best = v; bidx = tid; }
    }
    // Scalar tail (indices larger than all vector indices: strict > suffices).
    {
        int t = tail_start + tid;
        if (t < C_CLASSES) {
            float v = __ldg(row + t);
            if (v > best) { best = v; bidx = t; }
        }
    }

    // Warp-level (val, idx) reduce, min-idx tie-break.
    #pragma unroll
    for (int off = 16; off > 0; off >>= 1) {
        float ov = __shfl_down_sync(0xffffffffu, best, off);
        int   oi = __shfl_down_sync(0xffffffffu, bidx, off);
        if (ov > best || (ov == best && oi < bidx)) { best = ov; bidx = oi; }
    }

    __shared__ float swv[NWARPS];
    __shared__ int   swi[NWARPS];
    __shared__ int   slabel;
    if ((tid & 31) == 0) { swv[tid >> 5] = best; swi[tid >> 5] = bidx; }
    __syncthreads();
    if (tid == 0) {
        float bv = swv[0]; int bi = swi[0];
        #pragma unroll
        for (int w = 1; w < NWARPS; w++) {
            if (swv[w] > bv || (swv[w] == bv && swi[w] < bi)) { bv = swv[w]; bi = swi[w]; }
        }
        slabel = bi;
    }
    __syncthreads();
    const int label = slabel;

    // Squared distance over D=96 via float4 (rows are 384 B = 16B-aligned).
    __shared__ float sdist[D_DIM / 4];
    if (tid < D_DIM / 4) {
        float4 f = __ldg((const float4*)(features + (size_t)n * D_DIM) + tid);
        float4 c = __ldg((const float4*)(centers + (size_t)label * D_DIM) + tid);
        float dx = f.x - c.x, dy = f.y - c.y, dz = f.z - c.z, dw = f.w - c.w;
        sdist[tid] = dx * dx + dy * dy + dz * dz + dw * dw;
    }
    __syncthreads();

    if (tid == 0) {
        float dist = 0.0f;
        #pragma unroll
        for (int i = 0; i < D_DIM / 4; i++) dist += sdist[i];
        dist = fminf(fmaxf(dist, EPSV), INFV);
        atomicAdd(out, dist / (float)N);
    }
}

extern "C" void kernel_launch(void* const* d_in, const int* in_sizes, int n_in,
                              void* d_out, int out_size) {
    const float* features = (const float*)d_in[0];  // [B,T,D] fp32
    const float* predicts = (const float*)d_in[1];  // [B,T,C] fp32
    const float* centers  = (const float*)d_in[2];  // [C,D]   fp32
    float* out = (float*)d_out;

    const int N = in_sizes[0] / D_DIM;  // B*T = 8192

    cl_init_out<<<1, 1>>>(out);
    center_loss_kernel<<<N, NTHREADS>>>(features, predicts, centers, out, N);
}

// round 3
// speedup vs baseline: 1.4562x; 1.1623x over previous
#include <cuda_runtime.h>
#include <cuda_bf16.h>
#include <cstdint>

#define C_CLASSES 6625
#define D_DIM     96
#define NTHREADS  256
#define NWARPS    (NTHREADS / 32)
#define EPSV      1e-7f
#define INFV      1e11f

// clip() applied to the masked-out zeros contributes (C-1)*EPS exactly.
__global__ void cl_init_out(float* out) {
    out[0] = (float)(C_CLASSES - 1) * EPSV;
}

__device__ __forceinline__ void cmp4(float4 q, int base, float& best, int& bidx) {
    if (q.x > best) { best = q.x; bidx = base;     }
    if (q.y > best) { best = q.y; bidx = base + 1; }
    if (q.z > best) { best = q.z; bidx = base + 2; }
    if (q.w > best) { best = q.w; bidx = base + 3; }
}

__global__ __launch_bounds__(NTHREADS, 8)
void center_loss_kernel(const float* __restrict__ features,  // [N, 96]
                        const float* __restrict__ predicts,  // [N, 6625]
                        const float* __restrict__ centers,   // [6625, 96]
                        float* __restrict__ out,
                        int N)
{
    const int n   = blockIdx.x;
    const int tid = threadIdx.x;
    const float* row = predicts + (size_t)n * C_CLASSES;

    // Row stride 6625 floats = 26500 B is only 4B-aligned -> per-row
    // alignment prologue so the vector body can use LDG.128 safely.
    const int mis = ((int)((uintptr_t)row >> 2)) & 3;
    const int p   = (4 - mis) & 3;                      // scalar prologue count
    const int nv  = (C_CLASSES - p) >> 2;               // float4 count (>= 1655)
    const int tail_start = p + (nv << 2);

    const float4* vrow = (const float4*)(row + p);

    float best = -3.402823466e38f;
    int   bidx = C_CLASSES;

    // Software-pipelined scan: <=4 float4s live at a time (regs <= 32),
    // MLP stays ~4.  v0..v3 are always in range (max 1023 < nv).
    float4 a0 = __ldg(vrow + tid);
    float4 a1 = __ldg(vrow + tid + 1 * NTHREADS);
    float4 a2 = __ldg(vrow + tid + 2 * NTHREADS);
    float4 a3 = __ldg(vrow + tid + 3 * NTHREADS);

    cmp4(a0, p + (tid << 2),                    best, bidx);
    float4 b0 = __ldg(vrow + tid + 4 * NTHREADS);
    cmp4(a1, p + ((tid + 1 * NTHREADS) << 2),   best, bidx);
    float4 b1 = __ldg(vrow + tid + 5 * NTHREADS);
    cmp4(a2, p + ((tid + 2 * NTHREADS) << 2),   best, bidx);
    const int v6 = tid + 6 * NTHREADS;
    float4 b2 = (v6 < nv) ? __ldg(vrow + v6)
                          : make_float4(-3.4e38f, -3.4e38f, -3.4e38f, -3.4e38f);
    cmp4(a3, p + ((tid + 3 * NTHREADS) << 2),   best, bidx);
    cmp4(b0, p + ((tid + 4 * NTHREADS) << 2),   best, bidx);
    cmp4(b1, p + ((tid + 5 * NTHREADS) << 2),   best, bidx);
    if (v6 < nv) cmp4(b2, p + (v6 << 2),        best, bidx);

    // Scalar prologue (indices below all vector indices: need tie-break).
    if (tid < p) {
        float v = __ldg(row + tid);
        if (v > best || (v == best && tid < bidx)) { best = v; bidx = tid; }
    }
    // Scalar tail (indices above all vector indices: strict > suffices).
    {
        int t = tail_start + tid;
        if (t < C_CLASSES) {
            float v = __ldg(row + t);
            if (v > best) { best = v; bidx = t; }
        }
    }

    // Warp-level (val, idx) reduce, min-idx tie-break.
    #pragma unroll
    for (int off = 16; off > 0; off >>= 1) {
        float ov = __shfl_down_sync(0xffffffffu, best, off);
        int   oi = __shfl_down_sync(0xffffffffu, bidx, off);
        if (ov > best || (ov == best && oi < bidx)) { best = ov; bidx = oi; }
    }

    __shared__ float swv[NWARPS];
    __shared__ int   swi[NWARPS];
    __shared__ int   slabel;
    if ((tid & 31) == 0) { swv[tid >> 5] = best; swi[tid >> 5] = bidx; }
    __syncthreads();
    if (tid == 0) {
        float bv = swv[0]; int bi = swi[0];
        #pragma unroll
        for (int w = 1; w < NWARPS; w++) {
            if (swv[w] > bv || (swv[w] == bv && swi[w] < bi)) { bv = swv[w]; bi = swi[w]; }
        }
        slabel = bi;
    }
    __syncthreads();

    // Squared distance over D=96: warp 0 only, 24 lanes x float4, shfl reduce.
    if (tid < 32) {
        const int label = slabel;
        float part = 0.0f;
        if (tid < D_DIM / 4) {
            float4 f = __ldg((const float4*)(features + (size_t)n * D_DIM) + tid);
            float4 c = __ldg((const float4*)(centers + (size_t)label * D_DIM) + tid);
            float dx = f.x - c.x, dy = f.y - c.y, dz = f.z - c.z, dw = f.w - c.w;
            part = dx * dx + dy * dy + dz * dz + dw * dw;
        }
        #pragma unroll
        for (int off = 16; off > 0; off >>= 1)
            part += __shfl_down_sync(0xffffffffu, part, off);
        if (tid == 0) {
            float dist = fminf(fmaxf(part, EPSV), INFV);
            atomicAdd(out, dist / (float)N);
        }
    }
}

extern "C" void kernel_launch(void* const* d_in, const int* in_sizes, int n_in,
                              void* d_out, int out_size) {
    const float* features = (const float*)d_in[0];  // [B,T,D] fp32
    const float* predicts = (const float*)d_in[1];  // [B,T,C] fp32
    const float* centers  = (const float*)d_in[2];  // [C,D]   fp32
    float* out = (float*)d_out;

    const int N = in_sizes[0] / D_DIM;  // B*T = 8192

    cl_init_out<<<1, 1>>>(out);
    center_loss_kernel<<<N, NTHREADS>>>(features, predicts, centers, out, N);
}